// round 7
// baseline (speedup 1.0000x reference)
#include <cuda_runtime.h>
#include <cuda_fp16.h>
#include <cstddef>
#include <cstdint>

#define NPROJ 180
#define DH    192
#define DW    384
#define NX    96
#define NY    96
#define NZ    96
#define NB    2
#define ZPT   4

// Scratch: 2x2 bilinear quads. g_q[v][u] = (t[v][u], t[v][u+1], t[v+1][u], t[v+1][u+1])
// packed as 4 halves in 8 bytes -> ONE LDG.64 fetches the full bilinear footprint. ~106 MB.
__device__ uint2 g_q[(size_t)NB * NPROJ * DH * DW];

__device__ __forceinline__ uint32_t h2_bits(__half2 h) {
    union { __half2 h; uint32_t u; } c; c.h = h; return c.u;
}
__device__ __forceinline__ __half2 bits_h2(uint32_t u) {
    union { uint32_t u; __half2 h; } c; c.u = u; return c.h;
}

__global__ void prep_quads(const float* __restrict__ sino) {
    const size_t total = (size_t)NB * NPROJ * DH * DW;
    size_t base = ((size_t)blockIdx.x * blockDim.x + threadIdx.x) * 4;
    if (base >= total) return;

    int v   = (int)((base / DW) % DH);
    int col = (int)(base % DW);

    float4 a = *(const float4*)(sino + base);
    float a4 = (col == DW - 4) ? a.w : __ldg(sino + base + 4);

    float4 bq; float b4;
    if (v < DH - 1) {
        bq = *(const float4*)(sino + base + DW);
        b4 = (col == DW - 4) ? bq.w : __ldg(sino + base + DW + 4);
    } else {
        bq = a; b4 = a4;   // clamp; interior geometry never samples this
    }

    uint2* o = g_q + base;
    o[0] = make_uint2(h2_bits(__floats2half2_rn(a.x, a.y)), h2_bits(__floats2half2_rn(bq.x, bq.y)));
    o[1] = make_uint2(h2_bits(__floats2half2_rn(a.y, a.z)), h2_bits(__floats2half2_rn(bq.y, bq.z)));
    o[2] = make_uint2(h2_bits(__floats2half2_rn(a.z, a.w)), h2_bits(__floats2half2_rn(bq.z, bq.w)));
    o[3] = make_uint2(h2_bits(__floats2half2_rn(a.w, a4 )), h2_bits(__floats2half2_rn(bq.w, b4 )));
}

__global__ __launch_bounds__(NX, 14)
void cone_bp_kernel(const float* __restrict__ mats,   // [P, 3, 4]
                    float* __restrict__ out)          // [B, Z, Y, X]
{
    // Cone-beam geometry: P[0][2] == P[2][2] == 0 -> u, w independent of z;
    // v affine in z. Fold y into per-projection coefficients once per block.
    __shared__ float4 sA[NPROJ];   // (P0, P1*y+P3, P8, P9*y+P11)   u and w parts
    __shared__ float4 sB[NPROJ];   // (P4, P5*y+P7, P6, -)          v part

    const int y  = blockIdx.x;
    const int zc = blockIdx.y;     // z-chunk of ZPT voxels
    const int b  = blockIdx.z;
    const int tx = threadIdx.x;    // x voxel

    const float yw = (float)y - 47.5f;
    for (int p = tx; p < NPROJ; p += NX) {
        const float* P = mats + p * 12;
        sA[p] = make_float4(P[0], fmaf(P[1], yw, P[3]),
                            P[8], fmaf(P[9], yw, P[11]));
        sB[p] = make_float4(P[4], fmaf(P[5], yw, P[7]), P[6], 0.0f);
    }
    __syncthreads();

    const float xw  = (float)tx - 47.5f;
    const float zw0 = (float)(zc * ZPT) - 47.5f;

    float acc[ZPT];
    #pragma unroll
    for (int j = 0; j < ZPT; ++j) acc[j] = 0.0f;

    const char* pbase = (const char*)(g_q + (size_t)b * NPROJ * DH * DW);

    #pragma unroll 2
    for (int p = 0; p < NPROJ; ++p) {
        const float4 A = sA[p];
        const float4 B = sB[p];
        const char* img = pbase + (size_t)p * ((size_t)DH * DW * 8);

        float uw = fmaf(A.x, xw, A.y);
        float w  = fmaf(A.z, xw, A.w);
        float rw;
        asm("rcp.approx.f32 %0, %1;" : "=f"(rw) : "f"(w));

        float u   = uw * rw;
        float iw2 = rw * rw;

        float uf = floorf(u);
        int   ui = (int)uf;
        float fu = u - uf;
        float wa = iw2 * (1.0f - fu);   // weight for left column
        float wb = iw2 * fu;            // weight for right column

        float vw0 = fmaf(B.x, xw, B.y);
        float v0  = fmaf(B.z, zw0, vw0) * rw;   // v at first z of chunk
        float dv  = B.z * rw;                   // per-z increment

        const char* cb = img + (size_t)ui * 8;

        // Addresses + vertical weights first, then batch the loads for MLP.
        int   vi[ZPT];
        float fv[ZPT];
        #pragma unroll
        for (int j = 0; j < ZPT; ++j) {
            float v  = fmaf(dv, (float)j, v0);
            float vf = floorf(v);
            vi[j] = (int)vf;
            fv[j] = v - vf;
        }

        uint2 q[ZPT];
        #pragma unroll
        for (int j = 0; j < ZPT; ++j)
            q[j] = __ldg((const uint2*)(cb + (size_t)vi[j] * (DW * 8)));

        #pragma unroll
        for (int j = 0; j < ZPT; ++j) {
            __half2 lo  = bits_h2(q[j].x);     // (t00, t01) row v
            __half2 hi  = bits_h2(q[j].y);     // (t10, t11) row v+1
            __half2 fv2 = __float2half2_rn(fv[j]);
            __half2 c   = __hfma2(fv2, __hsub2(hi, lo), lo);  // vertical lerp
            acc[j] = fmaf(wa, __low2float(c), fmaf(wb, __high2float(c), acc[j]));
        }
    }

    float* o = out + (((size_t)b * NZ + (size_t)(zc * ZPT)) * NY + y) * NX + tx;
    #pragma unroll
    for (int j = 0; j < ZPT; ++j) o[(size_t)j * NY * NX] = acc[j];
}

extern "C" void kernel_launch(void* const* d_in, const int* in_sizes, int n_in,
                              void* d_out, int out_size)
{
    const float* sino = (const float*)d_in[0];
    const float* mats = (const float*)d_in[1];
    if (n_in >= 2 && in_sizes[0] == NPROJ * 12) {
        sino = (const float*)d_in[1];
        mats = (const float*)d_in[0];
    }
    float* out = (float*)d_out;

    const size_t total  = (size_t)NB * NPROJ * DH * DW;
    const size_t groups = total / 4;
    prep_quads<<<(unsigned)((groups + 255) / 256), 256>>>(sino);

    dim3 grid(NY, NZ / ZPT, NB);
    cone_bp_kernel<<<grid, NX>>>(mats, out);
}

// round 11
// speedup vs baseline: 1.1925x; 1.1925x over previous
#include <cuda_runtime.h>
#include <cuda_fp16.h>
#include <cstddef>
#include <cstdint>

#define NPROJ 180
#define DH    192
#define DW    384
#define NX    96
#define NY    96
#define NZ    96
#define NB    2
#define ZPT   2
#define PHW   ((size_t)NPROJ * DH * DW)

// Scratch: batch-fused bilinear quads at each (p, v, u):
//   .x = (b0: t[v][u],   t[v][u+1])   .y = (b0: t[v+1][u], t[v+1][u+1])
//   .z = (b1: t[v][u],   t[v][u+1])   .w = (b1: t[v+1][u], t[v+1][u+1])
// One LDG.128 fetches the full 2x2 footprint for BOTH batches. ~212 MB.
__device__ uint4 g_q[PHW];

__device__ __forceinline__ uint32_t h2_bits(__half2 h) {
    union { __half2 h; uint32_t u; } c; c.h = h; return c.u;
}
__device__ __forceinline__ __half2 bits_h2(uint32_t u) {
    union { uint32_t u; __half2 h; } c; c.u = u; return c.h;
}

__global__ void prep_quads(const float* __restrict__ sino) {
    size_t base = ((size_t)blockIdx.x * blockDim.x + threadIdx.x) * 4;
    if (base >= PHW) return;

    int v   = (int)((base / DW) % DH);
    int col = (int)(base % DW);
    bool lastv = (v == DH - 1);
    bool lastc = (col == DW - 4);

    // batch 0: row v and v+1
    float4 a0 = *(const float4*)(sino + base);
    float  a0n = lastc ? a0.w : __ldg(sino + base + 4);
    float4 c0; float c0n;
    if (!lastv) { c0 = *(const float4*)(sino + base + DW);
                  c0n = lastc ? c0.w : __ldg(sino + base + DW + 4); }
    else        { c0 = a0; c0n = a0n; }

    // batch 1
    float4 a1 = *(const float4*)(sino + base + PHW);
    float  a1n = lastc ? a1.w : __ldg(sino + base + PHW + 4);
    float4 c1; float c1n;
    if (!lastv) { c1 = *(const float4*)(sino + base + PHW + DW);
                  c1n = lastc ? c1.w : __ldg(sino + base + PHW + DW + 4); }
    else        { c1 = a1; c1n = a1n; }

    uint4* o = g_q + base;
    o[0] = make_uint4(h2_bits(__floats2half2_rn(a0.x, a0.y)), h2_bits(__floats2half2_rn(c0.x, c0.y)),
                      h2_bits(__floats2half2_rn(a1.x, a1.y)), h2_bits(__floats2half2_rn(c1.x, c1.y)));
    o[1] = make_uint4(h2_bits(__floats2half2_rn(a0.y, a0.z)), h2_bits(__floats2half2_rn(c0.y, c0.z)),
                      h2_bits(__floats2half2_rn(a1.y, a1.z)), h2_bits(__floats2half2_rn(c1.y, c1.z)));
    o[2] = make_uint4(h2_bits(__floats2half2_rn(a0.z, a0.w)), h2_bits(__floats2half2_rn(c0.z, c0.w)),
                      h2_bits(__floats2half2_rn(a1.z, a1.w)), h2_bits(__floats2half2_rn(c1.z, c1.w)));
    o[3] = make_uint4(h2_bits(__floats2half2_rn(a0.w, a0n)),  h2_bits(__floats2half2_rn(c0.w, c0n)),
                      h2_bits(__floats2half2_rn(a1.w, a1n)),  h2_bits(__floats2half2_rn(c1.w, c1n)));
}

__global__ __launch_bounds__(NX, 16)
void cone_bp_kernel(const float* __restrict__ mats,   // [P, 3, 4]
                    float* __restrict__ out)          // [B, Z, Y, X]
{
    // Cone-beam geometry: P[0][2] == P[2][2] == 0 -> u, w independent of z;
    // v affine in z. Both batches share ALL geometry -> fused.
    __shared__ float4 sA[NPROJ];   // (P0, P1*y+P3, P8, P9*y+P11)
    __shared__ float4 sB[NPROJ];   // (P4, P5*y+P7, P6, -)

    const int y  = blockIdx.x;
    const int zc = blockIdx.y;     // z-chunk of ZPT voxels
    const int tx = threadIdx.x;    // x voxel

    const float yw = (float)y - 47.5f;
    for (int p = tx; p < NPROJ; p += NX) {
        const float* P = mats + p * 12;
        sA[p] = make_float4(P[0], fmaf(P[1], yw, P[3]),
                            P[8], fmaf(P[9], yw, P[11]));
        sB[p] = make_float4(P[4], fmaf(P[5], yw, P[7]), P[6], 0.0f);
    }
    __syncthreads();

    const float xw  = (float)tx - 47.5f;
    const float zw0 = (float)(zc * ZPT) - 47.5f;

    float acc0[ZPT], acc1[ZPT];
    #pragma unroll
    for (int j = 0; j < ZPT; ++j) { acc0[j] = 0.0f; acc1[j] = 0.0f; }

    #pragma unroll 2
    for (int p = 0; p < NPROJ; ++p) {
        const float4 A = sA[p];
        const float4 B = sB[p];
        const char* img = (const char*)(g_q + (size_t)p * (DH * DW));

        float uw = fmaf(A.x, xw, A.y);
        float w  = fmaf(A.z, xw, A.w);
        float rw;
        asm("rcp.approx.f32 %0, %1;" : "=f"(rw) : "f"(w));

        float u   = uw * rw;
        float iw2 = rw * rw;

        float uf = floorf(u);
        int   ui = (int)uf;
        float fu = u - uf;
        float wa = iw2 * (1.0f - fu);
        float wb = iw2 * fu;

        float vw0 = fmaf(B.x, xw, B.y);
        float v0  = fmaf(B.z, zw0, vw0) * rw;
        float dv  = B.z * rw;

        const char* cb = img + (size_t)ui * 16;

        int   vi[ZPT];
        float fv[ZPT];
        #pragma unroll
        for (int j = 0; j < ZPT; ++j) {
            float v  = fmaf(dv, (float)j, v0);
            float vf = floorf(v);
            vi[j] = (int)vf;
            fv[j] = v - vf;
        }

        uint4 q[ZPT];
        #pragma unroll
        for (int j = 0; j < ZPT; ++j)
            q[j] = __ldg((const uint4*)(cb + (size_t)vi[j] * (DW * 16)));

        #pragma unroll
        for (int j = 0; j < ZPT; ++j) {
            __half2 fv2 = __float2half2_rn(fv[j]);
            // batch 0
            __half2 lo0 = bits_h2(q[j].x), hi0 = bits_h2(q[j].y);
            __half2 c0  = __hfma2(fv2, __hsub2(hi0, lo0), lo0);
            acc0[j] = fmaf(wa, __low2float(c0), fmaf(wb, __high2float(c0), acc0[j]));
            // batch 1
            __half2 lo1 = bits_h2(q[j].z), hi1 = bits_h2(q[j].w);
            __half2 c1  = __hfma2(fv2, __hsub2(hi1, lo1), lo1);
            acc1[j] = fmaf(wa, __low2float(c1), fmaf(wb, __high2float(c1), acc1[j]));
        }
    }

    const size_t zbase = (size_t)zc * ZPT;
    #pragma unroll
    for (int j = 0; j < ZPT; ++j) {
        out[((zbase + j) * NY + y) * NX + tx]                       = acc0[j];
        out[(((size_t)NZ + zbase + j) * NY + y) * NX + tx]          = acc1[j];
    }
}

extern "C" void kernel_launch(void* const* d_in, const int* in_sizes, int n_in,
                              void* d_out, int out_size)
{
    const float* sino = (const float*)d_in[0];
    const float* mats = (const float*)d_in[1];
    if (n_in >= 2 && in_sizes[0] == NPROJ * 12) {
        sino = (const float*)d_in[1];
        mats = (const float*)d_in[0];
    }
    float* out = (float*)d_out;

    const size_t groups = PHW / 4;
    prep_quads<<<(unsigned)((groups + 255) / 256), 256>>>(sino);

    dim3 grid(NY, NZ / ZPT, 1);
    cone_bp_kernel<<<grid, NX>>>(mats, out);
}

// round 12
// speedup vs baseline: 1.2550x; 1.0524x over previous
#include <cuda_runtime.h>
#include <cuda_fp16.h>
#include <cstddef>
#include <cstdint>

#define NPROJ 180
#define DH    192
#define DW    384
#define NX    96
#define NY    96
#define NZ    96
#define ZPT   2
#define PHW   ((size_t)NPROJ * DH * DW)

// Scratch: batch-fused bilinear quads at each (p, v, u):
//   .x = (b0: t[v][u], t[v][u+1])   .y = (b0: t[v+1][u], t[v+1][u+1])
//   .z = (b1: t[v][u], t[v][u+1])   .w = (b1: t[v+1][u], t[v+1][u+1])
// One LDG.128 fetches the full 2x2 footprint for BOTH batches. ~212 MB.
__device__ uint4 g_q[PHW];

__device__ __forceinline__ uint32_t h2_bits(__half2 h) {
    union { __half2 h; uint32_t u; } c; c.h = h; return c.u;
}
__device__ __forceinline__ __half2 bits_h2(uint32_t u) {
    union { uint32_t u; __half2 h; } c; c.u = u; return c.h;
}

__global__ void prep_quads(const float* __restrict__ sino) {
    size_t base = ((size_t)blockIdx.x * blockDim.x + threadIdx.x) * 4;
    if (base >= PHW) return;

    int v   = (int)((base / DW) % DH);
    int col = (int)(base % DW);
    bool lastv = (v == DH - 1);
    bool lastc = (col == DW - 4);

    float4 a0 = *(const float4*)(sino + base);
    float  a0n = lastc ? a0.w : __ldg(sino + base + 4);
    float4 c0; float c0n;
    if (!lastv) { c0 = *(const float4*)(sino + base + DW);
                  c0n = lastc ? c0.w : __ldg(sino + base + DW + 4); }
    else        { c0 = a0; c0n = a0n; }

    float4 a1 = *(const float4*)(sino + base + PHW);
    float  a1n = lastc ? a1.w : __ldg(sino + base + PHW + 4);
    float4 c1; float c1n;
    if (!lastv) { c1 = *(const float4*)(sino + base + PHW + DW);
                  c1n = lastc ? c1.w : __ldg(sino + base + PHW + DW + 4); }
    else        { c1 = a1; c1n = a1n; }

    uint4* o = g_q + base;
    o[0] = make_uint4(h2_bits(__floats2half2_rn(a0.x, a0.y)), h2_bits(__floats2half2_rn(c0.x, c0.y)),
                      h2_bits(__floats2half2_rn(a1.x, a1.y)), h2_bits(__floats2half2_rn(c1.x, c1.y)));
    o[1] = make_uint4(h2_bits(__floats2half2_rn(a0.y, a0.z)), h2_bits(__floats2half2_rn(c0.y, c0.z)),
                      h2_bits(__floats2half2_rn(a1.y, a1.z)), h2_bits(__floats2half2_rn(c1.y, c1.z)));
    o[2] = make_uint4(h2_bits(__floats2half2_rn(a0.z, a0.w)), h2_bits(__floats2half2_rn(c0.z, c0.w)),
                      h2_bits(__floats2half2_rn(a1.z, a1.w)), h2_bits(__floats2half2_rn(c1.z, c1.w)));
    o[3] = make_uint4(h2_bits(__floats2half2_rn(a0.w, a0n)),  h2_bits(__floats2half2_rn(c0.w, c0n)),
                      h2_bits(__floats2half2_rn(a1.w, a1n)),  h2_bits(__floats2half2_rn(c1.w, c1n)));
}

__global__ __launch_bounds__(NX, 14)
void cone_bp_kernel(const float* __restrict__ mats,   // [P, 3, 4]
                    float* __restrict__ out)          // [B, Z, Y, X]
{
    // Cone-beam geometry: P[0][2] == P[2][2] == 0 -> u, w independent of z;
    // v affine in z. Both batches share ALL geometry -> fused.
    __shared__ float4 sA[NPROJ];   // (P0, P1*y+P3, P8, P9*y+P11)
    __shared__ float4 sB[NPROJ];   // (P4, P5*y+P7, P6, -)

    const int y  = blockIdx.x;
    const int zc = blockIdx.y;
    const int tx = threadIdx.x;

    const float yw = (float)y - 47.5f;
    for (int p = tx; p < NPROJ; p += NX) {
        const float* P = mats + p * 12;
        sA[p] = make_float4(P[0], fmaf(P[1], yw, P[3]),
                            P[8], fmaf(P[9], yw, P[11]));
        sB[p] = make_float4(P[4], fmaf(P[5], yw, P[7]), P[6], 0.0f);
    }
    __syncthreads();

    const float xw  = (float)tx - 47.5f;
    const float zw0 = (float)(zc * ZPT) - 47.5f;

    float acc0[ZPT], acc1[ZPT];
    #pragma unroll
    for (int j = 0; j < ZPT; ++j) { acc0[j] = 0.0f; acc1[j] = 0.0f; }

    // Process TWO projections per iteration in three phases:
    //   (1) all geometry + addresses, (2) all 4 LDG.128s, (3) all math.
    // Doubles loads-in-flight per scoreboard wait vs per-p structure.
    #pragma unroll 1
    for (int p = 0; p < NPROJ; p += 2) {
        float   wa[2], wb[2];
        __half2 fv2[2][ZPT];
        const char* addr[2][ZPT];

        #pragma unroll
        for (int s = 0; s < 2; ++s) {
            const float4 A = sA[p + s];
            const float4 B = sB[p + s];
            const char* img = (const char*)(g_q + (size_t)(p + s) * (DH * DW));

            float uw = fmaf(A.x, xw, A.y);
            float w  = fmaf(A.z, xw, A.w);
            float rw;
            asm("rcp.approx.f32 %0, %1;" : "=f"(rw) : "f"(w));

            float u   = uw * rw;
            float iw2 = rw * rw;

            float uf = floorf(u);
            int   ui = (int)uf;
            float fu = u - uf;
            wa[s] = iw2 * (1.0f - fu);
            wb[s] = iw2 * fu;

            float vw0 = fmaf(B.x, xw, B.y);
            float v0  = fmaf(B.z, zw0, vw0) * rw;
            float dv  = B.z * rw;

            const char* cb = img + (size_t)ui * 16;
            #pragma unroll
            for (int j = 0; j < ZPT; ++j) {
                float v  = fmaf(dv, (float)j, v0);
                float vf = floorf(v);
                fv2[s][j]  = __float2half2_rn(v - vf);
                addr[s][j] = cb + (size_t)(int)vf * (DW * 16);
            }
        }

        uint4 q[2][ZPT];
        #pragma unroll
        for (int s = 0; s < 2; ++s)
            #pragma unroll
            for (int j = 0; j < ZPT; ++j)
                q[s][j] = __ldg((const uint4*)addr[s][j]);

        #pragma unroll
        for (int s = 0; s < 2; ++s) {
            #pragma unroll
            for (int j = 0; j < ZPT; ++j) {
                __half2 lo0 = bits_h2(q[s][j].x), hi0 = bits_h2(q[s][j].y);
                __half2 c0  = __hfma2(fv2[s][j], __hsub2(hi0, lo0), lo0);
                acc0[j] = fmaf(wa[s], __low2float(c0), fmaf(wb[s], __high2float(c0), acc0[j]));

                __half2 lo1 = bits_h2(q[s][j].z), hi1 = bits_h2(q[s][j].w);
                __half2 c1  = __hfma2(fv2[s][j], __hsub2(hi1, lo1), lo1);
                acc1[j] = fmaf(wa[s], __low2float(c1), fmaf(wb[s], __high2float(c1), acc1[j]));
            }
        }
    }

    const size_t zbase = (size_t)zc * ZPT;
    #pragma unroll
    for (int j = 0; j < ZPT; ++j) {
        out[((zbase + j) * NY + y) * NX + tx]              = acc0[j];
        out[(((size_t)NZ + zbase + j) * NY + y) * NX + tx] = acc1[j];
    }
}

extern "C" void kernel_launch(void* const* d_in, const int* in_sizes, int n_in,
                              void* d_out, int out_size)
{
    const float* sino = (const float*)d_in[0];
    const float* mats = (const float*)d_in[1];
    if (n_in >= 2 && in_sizes[0] == NPROJ * 12) {
        sino = (const float*)d_in[1];
        mats = (const float*)d_in[0];
    }
    float* out = (float*)d_out;

    const size_t groups = PHW / 4;
    prep_quads<<<(unsigned)((groups + 255) / 256), 256>>>(sino);

    dim3 grid(NY, NZ / ZPT, 1);
    cone_bp_kernel<<<grid, NX>>>(mats, out);
}

// round 13
// speedup vs baseline: 1.3021x; 1.0375x over previous
#include <cuda_runtime.h>
#include <cuda_fp16.h>
#include <cstddef>
#include <cstdint>

#define NPROJ 180
#define DH    192
#define DW    384
#define NX    96
#define NY    96
#define NZ    96
#define ZPT   4
#define PHW   ((size_t)NPROJ * DH * DW)

// Scratch: batch-fused bilinear quads at each (p, v, u):
//   .x = (b0: t[v][u], t[v][u+1])   .y = (b0: t[v+1][u], t[v+1][u+1])
//   .z = (b1: t[v][u], t[v][u+1])   .w = (b1: t[v+1][u], t[v+1][u+1])
// One LDG.128 fetches the full 2x2 footprint for BOTH batches. ~212 MB.
__device__ uint4 g_q[PHW];

__device__ __forceinline__ uint32_t h2_bits(__half2 h) {
    union { __half2 h; uint32_t u; } c; c.h = h; return c.u;
}
__device__ __forceinline__ __half2 bits_h2(uint32_t u) {
    union { uint32_t u; __half2 h; } c; c.u = u; return c.h;
}

__global__ void prep_quads(const float* __restrict__ sino) {
    size_t base = ((size_t)blockIdx.x * blockDim.x + threadIdx.x) * 4;
    if (base >= PHW) return;

    int v   = (int)((base / DW) % DH);
    int col = (int)(base % DW);
    bool lastv = (v == DH - 1);
    bool lastc = (col == DW - 4);

    float4 a0 = *(const float4*)(sino + base);
    float  a0n = lastc ? a0.w : __ldg(sino + base + 4);
    float4 c0; float c0n;
    if (!lastv) { c0 = *(const float4*)(sino + base + DW);
                  c0n = lastc ? c0.w : __ldg(sino + base + DW + 4); }
    else        { c0 = a0; c0n = a0n; }

    float4 a1 = *(const float4*)(sino + base + PHW);
    float  a1n = lastc ? a1.w : __ldg(sino + base + PHW + 4);
    float4 c1; float c1n;
    if (!lastv) { c1 = *(const float4*)(sino + base + PHW + DW);
                  c1n = lastc ? c1.w : __ldg(sino + base + PHW + DW + 4); }
    else        { c1 = a1; c1n = a1n; }

    uint4* o = g_q + base;
    o[0] = make_uint4(h2_bits(__floats2half2_rn(a0.x, a0.y)), h2_bits(__floats2half2_rn(c0.x, c0.y)),
                      h2_bits(__floats2half2_rn(a1.x, a1.y)), h2_bits(__floats2half2_rn(c1.x, c1.y)));
    o[1] = make_uint4(h2_bits(__floats2half2_rn(a0.y, a0.z)), h2_bits(__floats2half2_rn(c0.y, c0.z)),
                      h2_bits(__floats2half2_rn(a1.y, a1.z)), h2_bits(__floats2half2_rn(c1.y, c1.z)));
    o[2] = make_uint4(h2_bits(__floats2half2_rn(a0.z, a0.w)), h2_bits(__floats2half2_rn(c0.z, c0.w)),
                      h2_bits(__floats2half2_rn(a1.z, a1.w)), h2_bits(__floats2half2_rn(c1.z, c1.w)));
    o[3] = make_uint4(h2_bits(__floats2half2_rn(a0.w, a0n)),  h2_bits(__floats2half2_rn(c0.w, c0n)),
                      h2_bits(__floats2half2_rn(a1.w, a1n)),  h2_bits(__floats2half2_rn(c1.w, c1n)));
}

__global__ __launch_bounds__(NX, 12)
void cone_bp_kernel(const float* __restrict__ mats,   // [P, 3, 4]
                    float* __restrict__ out)          // [B, Z, Y, X]
{
    // Cone-beam geometry: P[0][2] == P[2][2] == 0 -> u, w independent of z;
    // v affine in z. Both batches share ALL geometry -> fused.
    __shared__ float4 sA[NPROJ];   // (P0, P1*y+P3, P8, P9*y+P11)
    __shared__ float4 sB[NPROJ];   // (P4, P5*y+P7, P6, -)

    const int y  = blockIdx.x;
    const int zc = blockIdx.y;
    const int tx = threadIdx.x;

    const float yw = (float)y - 47.5f;
    for (int p = tx; p < NPROJ; p += NX) {
        const float* P = mats + p * 12;
        sA[p] = make_float4(P[0], fmaf(P[1], yw, P[3]),
                            P[8], fmaf(P[9], yw, P[11]));
        sB[p] = make_float4(P[4], fmaf(P[5], yw, P[7]), P[6], 0.0f);
    }
    __syncthreads();

    const float xw  = (float)tx - 47.5f;
    const float zw0 = (float)(zc * ZPT) - 47.5f;

    float acc0[ZPT], acc1[ZPT];
    #pragma unroll
    for (int j = 0; j < ZPT; ++j) { acc0[j] = 0.0f; acc1[j] = 0.0f; }

    // Two projections per iteration, pipelined:
    //   geom(s=0) -> loads(s=0) -> geom(s=1) -> loads(s=1) -> math(s=0) -> math(s=1)
    // 8 LDG.128s in flight per scoreboard drain; geometry of s=1 hides s=0 latency.
    float   wa[2], wb[2];
    __half2 fv2[2][ZPT];
    const char* addr[2][ZPT];
    uint4   q[2][ZPT];

    #pragma unroll 1
    for (int p = 0; p < NPROJ; p += 2) {
        #pragma unroll
        for (int s = 0; s < 2; ++s) {
            const float4 A = sA[p + s];
            const float4 B = sB[p + s];
            const char* img = (const char*)(g_q + (size_t)(p + s) * (DH * DW));

            float uw = fmaf(A.x, xw, A.y);
            float w  = fmaf(A.z, xw, A.w);
            float rw;
            asm("rcp.approx.f32 %0, %1;" : "=f"(rw) : "f"(w));

            float u   = uw * rw;
            float iw2 = rw * rw;

            float uf = floorf(u);
            int   ui = (int)uf;
            float fu = u - uf;
            wb[s] = iw2 * fu;
            wa[s] = iw2 - wb[s];

            float vw0 = fmaf(B.x, xw, B.y);
            float v0  = fmaf(B.z, zw0, vw0) * rw;
            float dv  = B.z * rw;

            const char* cb = img + (size_t)ui * 16;
            #pragma unroll
            for (int j = 0; j < ZPT; ++j) {
                float v  = fmaf(dv, (float)j, v0);
                float vf = floorf(v);
                fv2[s][j]  = __float2half2_rn(v - vf);
                addr[s][j] = cb + (size_t)(int)vf * (DW * 16);
            }
            // Issue this projection's loads immediately; s=1 geometry overlaps.
            #pragma unroll
            for (int j = 0; j < ZPT; ++j)
                q[s][j] = __ldg((const uint4*)addr[s][j]);
        }

        #pragma unroll
        for (int s = 0; s < 2; ++s) {
            #pragma unroll
            for (int j = 0; j < ZPT; ++j) {
                __half2 lo0 = bits_h2(q[s][j].x), hi0 = bits_h2(q[s][j].y);
                __half2 c0  = __hfma2(fv2[s][j], __hsub2(hi0, lo0), lo0);
                acc0[j] = fmaf(wa[s], __low2float(c0), fmaf(wb[s], __high2float(c0), acc0[j]));

                __half2 lo1 = bits_h2(q[s][j].z), hi1 = bits_h2(q[s][j].w);
                __half2 c1  = __hfma2(fv2[s][j], __hsub2(hi1, lo1), lo1);
                acc1[j] = fmaf(wa[s], __low2float(c1), fmaf(wb[s], __high2float(c1), acc1[j]));
            }
        }
    }

    const size_t zbase = (size_t)zc * ZPT;
    #pragma unroll
    for (int j = 0; j < ZPT; ++j) {
        out[((zbase + j) * NY + y) * NX + tx]              = acc0[j];
        out[(((size_t)NZ + zbase + j) * NY + y) * NX + tx] = acc1[j];
    }
}

extern "C" void kernel_launch(void* const* d_in, const int* in_sizes, int n_in,
                              void* d_out, int out_size)
{
    const float* sino = (const float*)d_in[0];
    const float* mats = (const float*)d_in[1];
    if (n_in >= 2 && in_sizes[0] == NPROJ * 12) {
        sino = (const float*)d_in[1];
        mats = (const float*)d_in[0];
    }
    float* out = (float*)d_out;

    const size_t groups = PHW / 4;
    prep_quads<<<(unsigned)((groups + 255) / 256), 256>>>(sino);

    dim3 grid(NY, NZ / ZPT, 1);
    cone_bp_kernel<<<grid, NX>>>(mats, out);
}